// round 3
// baseline (speedup 1.0000x reference)
#include <cuda_runtime.h>
#include <math_constants.h>

#define B_ 1024
#define Q_ 100
#define C_ 81
#define NCLS 80
#define V_ 117
#define THR 0.7f

// Scratch for rare conflict path (no dynamic allocation allowed)
__device__ unsigned      g_conf[B_][Q_][4];
__device__ int           g_m[B_];
__device__ unsigned char g_list[B_][Q_];

__device__ __forceinline__ float iou_f(const float* a, const float* b) {
    float area1 = (a[2] - a[0]) * (a[3] - a[1]);
    float area2 = (b[2] - b[0]) * (b[3] - b[1]);
    float ltx = fmaxf(a[0], b[0]), lty = fmaxf(a[1], b[1]);
    float rbx = fminf(a[2], b[2]), rby = fminf(a[3], b[3]);
    float w = fmaxf(rbx - ltx, 0.f), h = fmaxf(rby - lty, 0.f);
    float inter = w * h;
    float uni = area1 + area2 - inter;
    return inter / uni;  // 0/0 -> NaN, NaN > THR is false (matches JAX)
}

__global__ __launch_bounds__(128)
void kernA(const float* __restrict__ obj_logits,
           const float* __restrict__ verb_logits,
           const float* __restrict__ sub_boxes,
           const float* __restrict__ obj_boxes,
           const int*   __restrict__ tsz,
           float* __restrict__ out)
{
    int b    = blockIdx.x;
    int tid  = threadIdx.x;
    int lane = tid & 31;
    int warp = tid >> 5;

    __shared__ float    s_score[Q_];
    __shared__ int      s_label[Q_];
    __shared__ float    s_sb[Q_][4];
    __shared__ float    s_ob[Q_][4];
    __shared__ unsigned s_conf[Q_][4];
    __shared__ int      s_m;

    float img_h = (float)tsz[b * 2 + 0];
    float img_w = (float)tsz[b * 2 + 1];

    // ---- softmax over C=81 + max/argmax over first 80: one warp per query ----
    for (int q = warp; q < Q_; q += 4) {
        const float* lg = obj_logits + ((size_t)b * Q_ + q) * C_;
        float l0 = lg[lane];          // c in [0,32)
        float l1 = lg[lane + 32];     // c in [32,64)
        bool  has2 = (lane + 64) < C_;  // c in [64,81)
        float l2 = has2 ? lg[lane + 64] : -CUDART_INF_F;

        float mx = fmaxf(l0, fmaxf(l1, l2));
        #pragma unroll
        for (int o = 16; o; o >>= 1) mx = fmaxf(mx, __shfl_xor_sync(0xffffffffu, mx, o));

        float e = __expf(l0 - mx) + __expf(l1 - mx) + (has2 ? __expf(l2 - mx) : 0.f);
        #pragma unroll
        for (int o = 16; o; o >>= 1) e += __shfl_xor_sync(0xffffffffu, e, o);

        // argmax over c < 80 (exclude last class); ties -> lowest index (stable)
        float bv = l0; int bi = lane;
        if (l1 > bv) { bv = l1; bi = lane + 32; }
        if ((lane + 64) < NCLS && l2 > bv) { bv = l2; bi = lane + 64; }
        #pragma unroll
        for (int o = 16; o; o >>= 1) {
            float ov = __shfl_xor_sync(0xffffffffu, bv, o);
            int   oi = __shfl_xor_sync(0xffffffffu, bi, o);
            if (ov > bv || (ov == bv && oi < bi)) { bv = ov; bi = oi; }
        }
        if (lane == 0) {
            s_score[q] = __expf(bv - mx) / e;
            s_label[q] = bi;
        }
    }
    __syncthreads();

    float* out_vs     = out;
    float* out_scores = out + (size_t)B_ * Q_ * V_;
    float* out_labels = out_scores + (size_t)B_ * Q_;
    float* out_boxes  = out_labels + (size_t)B_ * 2 * Q_;

    // ---- boxes (cxcywh->xyxy * scale), labels, scores ----
    for (int q = tid; q < Q_; q += 128) {
        float4 sb4 = ((const float4*)sub_boxes)[(size_t)b * Q_ + q];
        float sx0 = (sb4.x - 0.5f * sb4.z) * img_w;
        float sy0 = (sb4.y - 0.5f * sb4.w) * img_h;
        float sx1 = (sb4.x + 0.5f * sb4.z) * img_w;
        float sy1 = (sb4.y + 0.5f * sb4.w) * img_h;
        s_sb[q][0] = sx0; s_sb[q][1] = sy0; s_sb[q][2] = sx1; s_sb[q][3] = sy1;
        float4 so; so.x = sx0; so.y = sy0; so.z = sx1; so.w = sy1;
        ((float4*)out_boxes)[(size_t)b * 2 * Q_ + q] = so;

        float4 ob4 = ((const float4*)obj_boxes)[(size_t)b * Q_ + q];
        float ox0 = (ob4.x - 0.5f * ob4.z) * img_w;
        float oy0 = (ob4.y - 0.5f * ob4.w) * img_h;
        float ox1 = (ob4.x + 0.5f * ob4.z) * img_w;
        float oy1 = (ob4.y + 0.5f * ob4.w) * img_h;
        s_ob[q][0] = ox0; s_ob[q][1] = oy0; s_ob[q][2] = ox1; s_ob[q][3] = oy1;
        float4 oo; oo.x = ox0; oo.y = oy0; oo.z = ox1; oo.w = oy1;
        ((float4*)out_boxes)[(size_t)b * 2 * Q_ + Q_ + q] = oo;

        out_labels[(size_t)b * 2 * Q_ + q]      = 0.f;
        out_labels[(size_t)b * 2 * Q_ + Q_ + q] = (float)s_label[q];
        out_scores[(size_t)b * Q_ + q]          = s_score[q];

        s_conf[q][0] = 0u; s_conf[q][1] = 0u; s_conf[q][2] = 0u; s_conf[q][3] = 0u;
    }
    __syncthreads();

    // ---- vs = sigmoid(verb) * obj_score ----
    {
        const float* vb = verb_logits + (size_t)b * Q_ * V_;
        float*       vo = out_vs     + (size_t)b * Q_ * V_;
        for (int i = tid; i < Q_ * V_; i += 128) {
            float sc = s_score[i / V_];
            float x  = vb[i];
            vo[i] = sc / (1.f + __expf(-x));
        }
    }

    // ---- conflict bitmask: same label AND min(iou_sb, iou_ob) > 0.7 ----
    for (int p = tid; p < Q_ * Q_; p += 128) {
        int j = p / Q_, k = p - j * Q_;
        if (j >= k) continue;
        if (s_label[j] != s_label[k]) continue;                 // cheap early-out
        if (!(iou_f(s_sb[j], s_sb[k]) > THR)) continue;
        if (!(iou_f(s_ob[j], s_ob[k]) > THR)) continue;
        atomicOr(&s_conf[j][k >> 5], 1u << (k & 31));
        atomicOr(&s_conf[k][j >> 5], 1u << (j & 31));
    }
    __syncthreads();

    if (tid == 0) {
        int m = 0;
        for (int q = 0; q < Q_; q++)                            // ascending order!
            if (s_conf[q][0] | s_conf[q][1] | s_conf[q][2] | s_conf[q][3])
                g_list[b][m++] = (unsigned char)q;
        g_m[b] = m;
        s_m = m;
    }
    __syncthreads();

    if (s_m > 0) {
        for (int i = tid; i < Q_ * 4; i += 128)
            g_conf[b][i >> 2][i & 3] = s_conf[i >> 2][i & 3];
    }
}

__global__ __launch_bounds__(128)
void kernC(float* __restrict__ out_vs)
{
    int b = blockIdx.x;
    int m = g_m[b];
    if (m == 0) return;   // >99.9% of blocks exit here

    __shared__ unsigned char s_ql[Q_];
    __shared__ unsigned      s_adj[Q_][4];
    int tid = threadIdx.x;

    for (int i = tid; i < m; i += 128) s_ql[i] = g_list[b][i];
    __syncthreads();

    int nw = (m + 31) >> 5;
    // Compact adjacency over the conflicted subset (diagonal cleared)
    for (int p = tid; p < m * nw; p += 128) {
        int i = p / nw, w = p - i * nw;
        int qi = s_ql[i];
        unsigned bits = 0;
        int jend = min(m, (w + 1) << 5);
        for (int j = (w << 5); j < jend; j++) {
            if (j == i) continue;
            int qj = s_ql[j];
            if ((g_conf[b][qi][qj >> 5] >> (qj & 31)) & 1u) bits |= 1u << (j & 31);
        }
        s_adj[i][w] = bits;
    }
    __syncthreads();

    float* base = out_vs + (size_t)b * Q_ * V_;
    for (int v = tid; v < V_; v += 128) {
        unsigned alive[4] = {0, 0, 0, 0};
        unsigned supp[4]  = {0, 0, 0, 0};
        for (int w = 0; w < nw; w++) alive[w] = 0xffffffffu;
        int rem = m & 31;
        if (rem) alive[nw - 1] = (1u << rem) - 1u;

        for (;;) {
            unsigned any = 0;
            for (int w = 0; w < nw; w++) any |= alive[w];
            if (!any) break;

            // selection-max == greedy in stable descending-sort order:
            // scan ascending original index with strict '>' -> ties pick lowest index
            int best = -1; float bs = -CUDART_INF_F;
            for (int i = 0; i < m; i++) {
                if ((alive[i >> 5] >> (i & 31)) & 1u) {
                    float s = base[(int)s_ql[i] * V_ + v];
                    if (s > bs) { bs = s; best = i; }
                }
            }
            if (best < 0) break;  // safety (all-NaN)

            for (int w = 0; w < nw; w++) {
                unsigned k = alive[w] & s_adj[best][w];
                supp[w]  |= k;
                alive[w] &= ~k;
            }
            alive[best >> 5] &= ~(1u << (best & 31));
        }

        for (int i = 0; i < m; i++)
            if ((supp[i >> 5] >> (i & 31)) & 1u)
                base[(int)s_ql[i] * V_ + v] -= 1.0f;
    }
}

extern "C" void kernel_launch(void* const* d_in, const int* in_sizes, int n_in,
                              void* d_out, int out_size)
{
    const float* obj_logits  = (const float*)d_in[0];
    const float* verb_logits = (const float*)d_in[1];
    const float* sub_boxes   = (const float*)d_in[2];
    const float* obj_boxes   = (const float*)d_in[3];
    const int*   tsz         = (const int*)d_in[4];
    float* out = (float*)d_out;

    kernA<<<B_, 128>>>(obj_logits, verb_logits, sub_boxes, obj_boxes, tsz, out);
    kernC<<<B_, 128>>>(out);
}

// round 6
// speedup vs baseline: 1.5782x; 1.5782x over previous
#include <cuda_runtime.h>
#include <math_constants.h>

#define B_ 1024
#define Q_ 100
#define C_ 81
#define NCLS 80
#define V_ 117
#define THR 0.7f

// Scratch for rare conflict path (no dynamic allocation allowed)
__device__ unsigned      g_conf[B_][Q_][4];
__device__ int           g_m[B_];
__device__ unsigned char g_list[B_][Q_];

__device__ __forceinline__ float iou_f(const float* a, const float* b) {
    float area1 = (a[2] - a[0]) * (a[3] - a[1]);
    float area2 = (b[2] - b[0]) * (b[3] - b[1]);
    float ltx = fmaxf(a[0], b[0]), lty = fmaxf(a[1], b[1]);
    float rbx = fminf(a[2], b[2]), rby = fminf(a[3], b[3]);
    float w = fmaxf(rbx - ltx, 0.f), h = fmaxf(rby - lty, 0.f);
    float inter = w * h;
    float uni = area1 + area2 - inter;
    return inter / uni;  // 0/0 -> NaN, NaN > THR is false (matches JAX)
}

// ---------------------------------------------------------------------------
// Kernel A: per-image prep. softmax/argmax, boxes, labels, scores, conflicts.
// Logits staged through shared memory so the reduction chains hit LDS, not DRAM.
// ---------------------------------------------------------------------------
__global__ __launch_bounds__(256)
void kernA(const float* __restrict__ obj_logits,
           const float* __restrict__ sub_boxes,
           const float* __restrict__ obj_boxes,
           const int*   __restrict__ tsz,
           float* __restrict__ out)
{
    int b    = blockIdx.x;
    int tid  = threadIdx.x;
    int lane = tid & 31;
    int warp = tid >> 5;

    __shared__ float    s_lg[Q_ * C_];        // 8100 floats = 32.4 KB
    __shared__ float    s_score[Q_];
    __shared__ int      s_label[Q_];
    __shared__ float    s_sb[Q_][4];
    __shared__ float    s_ob[Q_][4];
    __shared__ unsigned s_conf[Q_][4];
    __shared__ int      s_m;

    float img_h = (float)tsz[b * 2 + 0];
    float img_w = (float)tsz[b * 2 + 1];

    // Bulk coalesced copy of this image's logits into shared (2025 float4s)
    {
        const float4* src = (const float4*)(obj_logits + (size_t)b * Q_ * C_);
        float4*       dst = (float4*)s_lg;
        #pragma unroll 4
        for (int i = tid; i < (Q_ * C_) / 4; i += 256)
            dst[i] = src[i];
    }
    __syncthreads();

    // ---- softmax over C=81 + max/argmax over first 80: one warp per query ----
    for (int q = warp; q < Q_; q += 8) {
        const float* lg = s_lg + q * C_;
        float l0 = lg[lane];                    // c in [0,32)
        float l1 = lg[lane + 32];               // c in [32,64)
        bool  has2 = (lane + 64) < C_;          // c in [64,81)
        float l2 = has2 ? lg[lane + 64] : -CUDART_INF_F;

        float mx = fmaxf(l0, fmaxf(l1, l2));
        #pragma unroll
        for (int o = 16; o; o >>= 1) mx = fmaxf(mx, __shfl_xor_sync(0xffffffffu, mx, o));

        float e = __expf(l0 - mx) + __expf(l1 - mx) + (has2 ? __expf(l2 - mx) : 0.f);
        #pragma unroll
        for (int o = 16; o; o >>= 1) e += __shfl_xor_sync(0xffffffffu, e, o);

        // argmax over c < 80 (exclude last class); ties -> lowest index (stable)
        float bv = l0; int bi = lane;
        if (l1 > bv) { bv = l1; bi = lane + 32; }
        if ((lane + 64) < NCLS && l2 > bv) { bv = l2; bi = lane + 64; }
        #pragma unroll
        for (int o = 16; o; o >>= 1) {
            float ov = __shfl_xor_sync(0xffffffffu, bv, o);
            int   oi = __shfl_xor_sync(0xffffffffu, bi, o);
            if (ov > bv || (ov == bv && oi < bi)) { bv = ov; bi = oi; }
        }
        if (lane == 0) {
            s_score[q] = __fdividef(__expf(bv - mx), e);
            s_label[q] = bi;
        }
    }
    __syncthreads();

    float* out_scores = out + (size_t)B_ * Q_ * V_;
    float* out_labels = out_scores + (size_t)B_ * Q_;
    float* out_boxes  = out_labels + (size_t)B_ * 2 * Q_;

    // ---- boxes (cxcywh->xyxy * scale), labels, scores ----
    for (int q = tid; q < Q_; q += 256) {
        float4 sb4 = ((const float4*)sub_boxes)[(size_t)b * Q_ + q];
        float sx0 = (sb4.x - 0.5f * sb4.z) * img_w;
        float sy0 = (sb4.y - 0.5f * sb4.w) * img_h;
        float sx1 = (sb4.x + 0.5f * sb4.z) * img_w;
        float sy1 = (sb4.y + 0.5f * sb4.w) * img_h;
        s_sb[q][0] = sx0; s_sb[q][1] = sy0; s_sb[q][2] = sx1; s_sb[q][3] = sy1;
        float4 so; so.x = sx0; so.y = sy0; so.z = sx1; so.w = sy1;
        ((float4*)out_boxes)[(size_t)b * 2 * Q_ + q] = so;

        float4 ob4 = ((const float4*)obj_boxes)[(size_t)b * Q_ + q];
        float ox0 = (ob4.x - 0.5f * ob4.z) * img_w;
        float oy0 = (ob4.y - 0.5f * ob4.w) * img_h;
        float ox1 = (ob4.x + 0.5f * ob4.z) * img_w;
        float oy1 = (ob4.y + 0.5f * ob4.w) * img_h;
        s_ob[q][0] = ox0; s_ob[q][1] = oy0; s_ob[q][2] = ox1; s_ob[q][3] = oy1;
        float4 oo; oo.x = ox0; oo.y = oy0; oo.z = ox1; oo.w = oy1;
        ((float4*)out_boxes)[(size_t)b * 2 * Q_ + Q_ + q] = oo;

        out_labels[(size_t)b * 2 * Q_ + q]      = 0.f;
        out_labels[(size_t)b * 2 * Q_ + Q_ + q] = (float)s_label[q];
        out_scores[(size_t)b * Q_ + q]          = s_score[q];

        s_conf[q][0] = 0u; s_conf[q][1] = 0u; s_conf[q][2] = 0u; s_conf[q][3] = 0u;
    }
    __syncthreads();

    // ---- conflict bitmask: same label AND min(iou_sb, iou_ob) > 0.7 ----
    for (int p = tid; p < Q_ * Q_; p += 256) {
        int j = p / Q_, k = p - j * Q_;
        if (j >= k) continue;
        if (s_label[j] != s_label[k]) continue;                 // cheap early-out
        if (!(iou_f(s_sb[j], s_sb[k]) > THR)) continue;
        if (!(iou_f(s_ob[j], s_ob[k]) > THR)) continue;
        atomicOr(&s_conf[j][k >> 5], 1u << (k & 31));
        atomicOr(&s_conf[k][j >> 5], 1u << (j & 31));
    }
    __syncthreads();

    if (tid == 0) {
        int m = 0;
        for (int q = 0; q < Q_; q++)                            // ascending order!
            if (s_conf[q][0] | s_conf[q][1] | s_conf[q][2] | s_conf[q][3])
                g_list[b][m++] = (unsigned char)q;
        g_m[b] = m;
        s_m = m;
    }
    __syncthreads();

    if (s_m > 0) {
        for (int i = tid; i < Q_ * 4; i += 256)
            g_conf[b][i >> 2][i & 3] = s_conf[i >> 2][i & 3];
    }
}

// ---------------------------------------------------------------------------
// Kernel VS: pure streaming vs = sigmoid(verb) * score. float4 grid-stride.
// Reads the score table (400 KB, L2-resident) written by kernA.
// ---------------------------------------------------------------------------
__global__ __launch_bounds__(256)
void kernVS(const float* __restrict__ verb_logits,
            float* __restrict__ out)
{
    const int n4 = (B_ * Q_ * V_) / 4;        // 2,995,200
    const float* __restrict__ scores = out + (size_t)B_ * Q_ * V_;
    const float4* __restrict__ src = (const float4*)verb_logits;
    float4* __restrict__ dst = (float4*)out;

    int stride = gridDim.x * blockDim.x;
    for (int i4 = blockIdx.x * blockDim.x + threadIdx.x; i4 < n4; i4 += stride) {
        float4 x = src[i4];
        int e = i4 * 4;
        float s0 = __ldg(&scores[(e + 0) / V_]);
        float s1 = __ldg(&scores[(e + 1) / V_]);
        float s2 = __ldg(&scores[(e + 2) / V_]);
        float s3 = __ldg(&scores[(e + 3) / V_]);
        float4 y;
        y.x = __fdividef(s0, 1.f + __expf(-x.x));
        y.y = __fdividef(s1, 1.f + __expf(-x.y));
        y.z = __fdividef(s2, 1.f + __expf(-x.z));
        y.w = __fdividef(s3, 1.f + __expf(-x.w));
        dst[i4] = y;
    }
}

// ---------------------------------------------------------------------------
// Kernel C: rare PNMS repair path (nearly all blocks early-exit)
// ---------------------------------------------------------------------------
__global__ __launch_bounds__(128)
void kernC(float* __restrict__ out_vs)
{
    int b = blockIdx.x;
    int m = g_m[b];
    if (m == 0) return;   // >99.9% of blocks exit here

    __shared__ unsigned char s_ql[Q_];
    __shared__ unsigned      s_adj[Q_][4];
    int tid = threadIdx.x;

    for (int i = tid; i < m; i += 128) s_ql[i] = g_list[b][i];
    __syncthreads();

    int nw = (m + 31) >> 5;
    // Compact adjacency over the conflicted subset (diagonal cleared)
    for (int p = tid; p < m * nw; p += 128) {
        int i = p / nw, w = p - i * nw;
        int qi = s_ql[i];
        unsigned bits = 0;
        int jend = min(m, (w + 1) << 5);
        for (int j = (w << 5); j < jend; j++) {
            if (j == i) continue;
            int qj = s_ql[j];
            if ((g_conf[b][qi][qj >> 5] >> (qj & 31)) & 1u) bits |= 1u << (j & 31);
        }
        s_adj[i][w] = bits;
    }
    __syncthreads();

    float* base = out_vs + (size_t)b * Q_ * V_;
    for (int v = tid; v < V_; v += 128) {
        unsigned alive[4] = {0, 0, 0, 0};
        unsigned supp[4]  = {0, 0, 0, 0};
        for (int w = 0; w < nw; w++) alive[w] = 0xffffffffu;
        int rem = m & 31;
        if (rem) alive[nw - 1] = (1u << rem) - 1u;

        for (;;) {
            unsigned any = 0;
            for (int w = 0; w < nw; w++) any |= alive[w];
            if (!any) break;

            // selection-max == greedy in stable descending-sort order:
            // scan ascending original index with strict '>' -> ties pick lowest index
            int best = -1; float bs = -CUDART_INF_F;
            for (int i = 0; i < m; i++) {
                if ((alive[i >> 5] >> (i & 31)) & 1u) {
                    float s = base[(int)s_ql[i] * V_ + v];
                    if (s > bs) { bs = s; best = i; }
                }
            }
            if (best < 0) break;  // safety (all-NaN)

            for (int w = 0; w < nw; w++) {
                unsigned k = alive[w] & s_adj[best][w];
                supp[w]  |= k;
                alive[w] &= ~k;
            }
            alive[best >> 5] &= ~(1u << (best & 31));
        }

        for (int i = 0; i < m; i++)
            if ((supp[i >> 5] >> (i & 31)) & 1u)
                base[(int)s_ql[i] * V_ + v] -= 1.0f;
    }
}

extern "C" void kernel_launch(void* const* d_in, const int* in_sizes, int n_in,
                              void* d_out, int out_size)
{
    const float* obj_logits  = (const float*)d_in[0];
    const float* verb_logits = (const float*)d_in[1];
    const float* sub_boxes   = (const float*)d_in[2];
    const float* obj_boxes   = (const float*)d_in[3];
    const int*   tsz         = (const int*)d_in[4];
    float* out = (float*)d_out;

    kernA<<<B_, 256>>>(obj_logits, sub_boxes, obj_boxes, tsz, out);
    kernVS<<<2048, 256>>>(verb_logits, out);
    kernC<<<B_, 128>>>(out);
}

// round 11
// speedup vs baseline: 1.7013x; 1.0780x over previous
#include <cuda_runtime.h>
#include <math_constants.h>

#define B_ 1024
#define Q_ 100
#define C_ 81
#define NCLS 80
#define V_ 117
#define THR 0.7f

// Scratch (no dynamic allocation allowed)
__device__ int           g_label[B_ * Q_];
__device__ unsigned      g_conf[B_][Q_][4];
__device__ int           g_m[B_];
__device__ unsigned char g_list[B_][Q_];

__device__ __forceinline__ float iou_f(const float* a, const float* b) {
    float area1 = (a[2] - a[0]) * (a[3] - a[1]);
    float area2 = (b[2] - b[0]) * (b[3] - b[1]);
    float ltx = fmaxf(a[0], b[0]), lty = fmaxf(a[1], b[1]);
    float rbx = fminf(a[2], b[2]), rby = fminf(a[3], b[3]);
    float w = fmaxf(rbx - ltx, 0.f), h = fmaxf(rby - lty, 0.f);
    float inter = w * h;
    float uni = area1 + area2 - inter;
    return inter / uni;  // 0/0 -> NaN, NaN > THR is false (matches JAX)
}

// ---------------------------------------------------------------------------
// Kernel 1: softmax over C=81 + max/argmax over first 80.
// One warp per query, 102,400 independent warps -> DRAM-latency fully hidden.
// Row load is fully coalesced (324 contiguous bytes per warp).
// ---------------------------------------------------------------------------
__global__ __launch_bounds__(256)
void kern1(const float* __restrict__ obj_logits,
           float* __restrict__ out)
{
    int g    = blockIdx.x * 8 + (threadIdx.x >> 5);   // global query id, < B_*Q_
    int lane = threadIdx.x & 31;

    const float* lg = obj_logits + (size_t)g * C_;
    float l0 = lg[lane];                    // c in [0,32)
    float l1 = lg[lane + 32];               // c in [32,64)
    bool  has2 = (lane + 64) < C_;          // c in [64,81)
    float l2 = has2 ? lg[lane + 64] : -CUDART_INF_F;

    float mx = fmaxf(l0, fmaxf(l1, l2));
    #pragma unroll
    for (int o = 16; o; o >>= 1) mx = fmaxf(mx, __shfl_xor_sync(0xffffffffu, mx, o));

    float e = __expf(l0 - mx) + __expf(l1 - mx) + (has2 ? __expf(l2 - mx) : 0.f);
    #pragma unroll
    for (int o = 16; o; o >>= 1) e += __shfl_xor_sync(0xffffffffu, e, o);

    // argmax over c < 80 (exclude last class); ties -> lowest index (stable)
    float bv = l0; int bi = lane;
    if (l1 > bv) { bv = l1; bi = lane + 32; }
    if ((lane + 64) < NCLS && l2 > bv) { bv = l2; bi = lane + 64; }
    #pragma unroll
    for (int o = 16; o; o >>= 1) {
        float ov = __shfl_xor_sync(0xffffffffu, bv, o);
        int   oi = __shfl_xor_sync(0xffffffffu, bi, o);
        if (ov > bv || (ov == bv && oi < bi)) { bv = ov; bi = oi; }
    }
    if (lane == 0) {
        float* out_scores = out + (size_t)B_ * Q_ * V_;
        out_scores[g] = __fdividef(__expf(bv - mx), e);
        g_label[g]    = bi;
    }
}

// ---------------------------------------------------------------------------
// Kernel 2: per-image boxes (cxcywh->xyxy*scale), labels out, conflict graph.
// ---------------------------------------------------------------------------
__global__ __launch_bounds__(256)
void kern2(const float* __restrict__ sub_boxes,
           const float* __restrict__ obj_boxes,
           const int*   __restrict__ tsz,
           float* __restrict__ out)
{
    int b   = blockIdx.x;
    int tid = threadIdx.x;

    __shared__ int      s_label[Q_];
    __shared__ float    s_sb[Q_][4];
    __shared__ float    s_ob[Q_][4];
    __shared__ unsigned s_conf[Q_][4];
    __shared__ int      s_m;

    float img_h = (float)tsz[b * 2 + 0];
    float img_w = (float)tsz[b * 2 + 1];

    float* out_scores = out + (size_t)B_ * Q_ * V_;
    float* out_labels = out_scores + (size_t)B_ * Q_;
    float* out_boxes  = out_labels + (size_t)B_ * 2 * Q_;

    for (int q = tid; q < Q_; q += 256) {
        int lbl = g_label[b * Q_ + q];
        s_label[q] = lbl;

        float4 sb4 = ((const float4*)sub_boxes)[(size_t)b * Q_ + q];
        float sx0 = (sb4.x - 0.5f * sb4.z) * img_w;
        float sy0 = (sb4.y - 0.5f * sb4.w) * img_h;
        float sx1 = (sb4.x + 0.5f * sb4.z) * img_w;
        float sy1 = (sb4.y + 0.5f * sb4.w) * img_h;
        s_sb[q][0] = sx0; s_sb[q][1] = sy0; s_sb[q][2] = sx1; s_sb[q][3] = sy1;
        float4 so; so.x = sx0; so.y = sy0; so.z = sx1; so.w = sy1;
        ((float4*)out_boxes)[(size_t)b * 2 * Q_ + q] = so;

        float4 ob4 = ((const float4*)obj_boxes)[(size_t)b * Q_ + q];
        float ox0 = (ob4.x - 0.5f * ob4.z) * img_w;
        float oy0 = (ob4.y - 0.5f * ob4.w) * img_h;
        float ox1 = (ob4.x + 0.5f * ob4.z) * img_w;
        float oy1 = (ob4.y + 0.5f * ob4.w) * img_h;
        s_ob[q][0] = ox0; s_ob[q][1] = oy0; s_ob[q][2] = ox1; s_ob[q][3] = oy1;
        float4 oo; oo.x = ox0; oo.y = oy0; oo.z = ox1; oo.w = oy1;
        ((float4*)out_boxes)[(size_t)b * 2 * Q_ + Q_ + q] = oo;

        out_labels[(size_t)b * 2 * Q_ + q]      = 0.f;
        out_labels[(size_t)b * 2 * Q_ + Q_ + q] = (float)lbl;

        s_conf[q][0] = 0u; s_conf[q][1] = 0u; s_conf[q][2] = 0u; s_conf[q][3] = 0u;
    }
    __syncthreads();

    // ---- conflict bitmask: same label AND min(iou_sb, iou_ob) > 0.7 ----
    for (int p = tid; p < Q_ * Q_; p += 256) {
        int j = p / Q_, k = p - j * Q_;
        if (j >= k) continue;
        if (s_label[j] != s_label[k]) continue;                 // cheap early-out
        if (!(iou_f(s_sb[j], s_sb[k]) > THR)) continue;
        if (!(iou_f(s_ob[j], s_ob[k]) > THR)) continue;
        atomicOr(&s_conf[j][k >> 5], 1u << (k & 31));
        atomicOr(&s_conf[k][j >> 5], 1u << (j & 31));
    }
    __syncthreads();

    if (tid == 0) {
        int m = 0;
        for (int q = 0; q < Q_; q++)                            // ascending order!
            if (s_conf[q][0] | s_conf[q][1] | s_conf[q][2] | s_conf[q][3])
                g_list[b][m++] = (unsigned char)q;
        g_m[b] = m;
        s_m = m;
    }
    __syncthreads();

    if (s_m > 0) {
        for (int i = tid; i < Q_ * 4; i += 256)
            g_conf[b][i >> 2][i & 3] = s_conf[i >> 2][i & 3];
    }
}

// ---------------------------------------------------------------------------
// Kernel VS: pure streaming vs = sigmoid(verb) * score. Already at LTS cap.
// ---------------------------------------------------------------------------
__global__ __launch_bounds__(256)
void kernVS(const float* __restrict__ verb_logits,
            float* __restrict__ out)
{
    const int n4 = (B_ * Q_ * V_) / 4;        // 2,995,200
    const float* __restrict__ scores = out + (size_t)B_ * Q_ * V_;
    const float4* __restrict__ src = (const float4*)verb_logits;
    float4* __restrict__ dst = (float4*)out;

    int stride = gridDim.x * blockDim.x;
    for (int i4 = blockIdx.x * blockDim.x + threadIdx.x; i4 < n4; i4 += stride) {
        float4 x = src[i4];
        int e = i4 * 4;
        float s0 = __ldg(&scores[(e + 0) / V_]);
        float s1 = __ldg(&scores[(e + 1) / V_]);
        float s2 = __ldg(&scores[(e + 2) / V_]);
        float s3 = __ldg(&scores[(e + 3) / V_]);
        float4 y;
        y.x = __fdividef(s0, 1.f + __expf(-x.x));
        y.y = __fdividef(s1, 1.f + __expf(-x.y));
        y.z = __fdividef(s2, 1.f + __expf(-x.z));
        y.w = __fdividef(s3, 1.f + __expf(-x.w));
        dst[i4] = y;
    }
}

// ---------------------------------------------------------------------------
// Kernel C: rare PNMS repair path (nearly all blocks early-exit)
// ---------------------------------------------------------------------------
__global__ __launch_bounds__(128)
void kernC(float* __restrict__ out_vs)
{
    int b = blockIdx.x;
    int m = g_m[b];
    if (m == 0) return;   // >99.9% of blocks exit here

    __shared__ unsigned char s_ql[Q_];
    __shared__ unsigned      s_adj[Q_][4];
    int tid = threadIdx.x;

    for (int i = tid; i < m; i += 128) s_ql[i] = g_list[b][i];
    __syncthreads();

    int nw = (m + 31) >> 5;
    // Compact adjacency over the conflicted subset (diagonal cleared)
    for (int p = tid; p < m * nw; p += 128) {
        int i = p / nw, w = p - i * nw;
        int qi = s_ql[i];
        unsigned bits = 0;
        int jend = min(m, (w + 1) << 5);
        for (int j = (w << 5); j < jend; j++) {
            if (j == i) continue;
            int qj = s_ql[j];
            if ((g_conf[b][qi][qj >> 5] >> (qj & 31)) & 1u) bits |= 1u << (j & 31);
        }
        s_adj[i][w] = bits;
    }
    __syncthreads();

    float* base = out_vs + (size_t)b * Q_ * V_;
    for (int v = tid; v < V_; v += 128) {
        unsigned alive[4] = {0, 0, 0, 0};
        unsigned supp[4]  = {0, 0, 0, 0};
        for (int w = 0; w < nw; w++) alive[w] = 0xffffffffu;
        int rem = m & 31;
        if (rem) alive[nw - 1] = (1u << rem) - 1u;

        for (;;) {
            unsigned any = 0;
            for (int w = 0; w < nw; w++) any |= alive[w];
            if (!any) break;

            // selection-max == greedy in stable descending-sort order:
            // scan ascending original index with strict '>' -> ties pick lowest index
            int best = -1; float bs = -CUDART_INF_F;
            for (int i = 0; i < m; i++) {
                if ((alive[i >> 5] >> (i & 31)) & 1u) {
                    float s = base[(int)s_ql[i] * V_ + v];
                    if (s > bs) { bs = s; best = i; }
                }
            }
            if (best < 0) break;  // safety (all-NaN)

            for (int w = 0; w < nw; w++) {
                unsigned k = alive[w] & s_adj[best][w];
                supp[w]  |= k;
                alive[w] &= ~k;
            }
            alive[best >> 5] &= ~(1u << (best & 31));
        }

        for (int i = 0; i < m; i++)
            if ((supp[i >> 5] >> (i & 31)) & 1u)
                base[(int)s_ql[i] * V_ + v] -= 1.0f;
    }
}

extern "C" void kernel_launch(void* const* d_in, const int* in_sizes, int n_in,
                              void* d_out, int out_size)
{
    const float* obj_logits  = (const float*)d_in[0];
    const float* verb_logits = (const float*)d_in[1];
    const float* sub_boxes   = (const float*)d_in[2];
    const float* obj_boxes   = (const float*)d_in[3];
    const int*   tsz         = (const int*)d_in[4];
    float* out = (float*)d_out;

    kern1<<<(B_ * Q_) / 8, 256>>>(obj_logits, out);
    kern2<<<B_, 256>>>(sub_boxes, obj_boxes, tsz, out);
    kernVS<<<2048, 256>>>(verb_logits, out);
    kernC<<<B_, 128>>>(out);
}

// round 12
// speedup vs baseline: 1.9953x; 1.1728x over previous
#include <cuda_runtime.h>
#include <math_constants.h>

#define B_ 1024
#define Q_ 100
#define C_ 81
#define NCLS 80
#define V_ 117
#define THR 0.7f

// Scratch (no dynamic allocation allowed)
__device__ int g_label[B_ * Q_];

__device__ __forceinline__ float iou_f(const float* a, const float* b) {
    float area1 = (a[2] - a[0]) * (a[3] - a[1]);
    float area2 = (b[2] - b[0]) * (b[3] - b[1]);
    float ltx = fmaxf(a[0], b[0]), lty = fmaxf(a[1], b[1]);
    float rbx = fminf(a[2], b[2]), rby = fminf(a[3], b[3]);
    float w = fmaxf(rbx - ltx, 0.f), h = fmaxf(rby - lty, 0.f);
    float inter = w * h;
    float uni = area1 + area2 - inter;
    return inter / uni;  // 0/0 -> NaN, NaN > THR is false (matches JAX)
}

// ---------------------------------------------------------------------------
// Kernel F (fused): one warp per query.
//   - softmax over C=81, max/argmax over first 80 (score ends up in ALL lanes)
//   - immediately streams vs[q, :] = sigmoid(verb[q, :]) * score
// Per-warp I/O ~1.3 KB coalesced; 102,400 independent warps hide all latency.
// ---------------------------------------------------------------------------
__global__ __launch_bounds__(256)
void kernF(const float* __restrict__ obj_logits,
           const float* __restrict__ verb_logits,
           float* __restrict__ out)
{
    int g    = blockIdx.x * 8 + (threadIdx.x >> 5);   // global query id, < B_*Q_
    int lane = threadIdx.x & 31;

    const float* lg = obj_logits + (size_t)g * C_;
    float l0 = lg[lane];                    // c in [0,32)
    float l1 = lg[lane + 32];               // c in [32,64)
    bool  has2 = (lane + 64) < C_;          // c in [64,81)
    float l2 = has2 ? lg[lane + 64] : -CUDART_INF_F;

    float mx = fmaxf(l0, fmaxf(l1, l2));
    #pragma unroll
    for (int o = 16; o; o >>= 1) mx = fmaxf(mx, __shfl_xor_sync(0xffffffffu, mx, o));

    float e = __expf(l0 - mx) + __expf(l1 - mx) + (has2 ? __expf(l2 - mx) : 0.f);
    #pragma unroll
    for (int o = 16; o; o >>= 1) e += __shfl_xor_sync(0xffffffffu, e, o);

    // argmax over c < 80 (exclude last class); ties -> lowest index (stable)
    float bv = l0; int bi = lane;
    if (l1 > bv) { bv = l1; bi = lane + 32; }
    if ((lane + 64) < NCLS && l2 > bv) { bv = l2; bi = lane + 64; }
    #pragma unroll
    for (int o = 16; o; o >>= 1) {
        float ov = __shfl_xor_sync(0xffffffffu, bv, o);
        int   oi = __shfl_xor_sync(0xffffffffu, bi, o);
        if (ov > bv || (ov == bv && oi < bi)) { bv = ov; bi = oi; }
    }

    // xor-reduction leaves identical (bv, e, mx) in every lane
    float score = __fdividef(__expf(bv - mx), e);

    if (lane == 0) {
        float* out_scores = out + (size_t)B_ * Q_ * V_;
        out_scores[g] = score;
        g_label[g]    = bi;
    }

    // ---- fused vs = sigmoid(verb) * score for this query's 117 classes ----
    const float* vb = verb_logits + (size_t)g * V_;
    float*       vo = out         + (size_t)g * V_;
    #pragma unroll
    for (int i = lane; i < V_; i += 32) {
        float x = vb[i];
        vo[i] = __fdividef(score, 1.f + __expf(-x));
    }
}

// ---------------------------------------------------------------------------
// Kernel G (fused): per-image boxes/labels + conflict graph + in-block PNMS
// repair (rare path; nearly all blocks skip it entirely).
// ---------------------------------------------------------------------------
__global__ __launch_bounds__(256)
void kernG(const float* __restrict__ sub_boxes,
           const float* __restrict__ obj_boxes,
           const int*   __restrict__ tsz,
           float* __restrict__ out)
{
    int b   = blockIdx.x;
    int tid = threadIdx.x;

    __shared__ int           s_label[Q_];
    __shared__ float         s_sb[Q_][4];
    __shared__ float         s_ob[Q_][4];
    __shared__ unsigned      s_conf[Q_][4];
    __shared__ int           s_m;
    __shared__ unsigned char s_ql[Q_];
    __shared__ unsigned      s_adj[Q_][4];

    float img_h = (float)tsz[b * 2 + 0];
    float img_w = (float)tsz[b * 2 + 1];

    float* out_scores = out + (size_t)B_ * Q_ * V_;
    float* out_labels = out_scores + (size_t)B_ * Q_;
    float* out_boxes  = out_labels + (size_t)B_ * 2 * Q_;

    for (int q = tid; q < Q_; q += 256) {
        int lbl = g_label[b * Q_ + q];
        s_label[q] = lbl;

        float4 sb4 = ((const float4*)sub_boxes)[(size_t)b * Q_ + q];
        float sx0 = (sb4.x - 0.5f * sb4.z) * img_w;
        float sy0 = (sb4.y - 0.5f * sb4.w) * img_h;
        float sx1 = (sb4.x + 0.5f * sb4.z) * img_w;
        float sy1 = (sb4.y + 0.5f * sb4.w) * img_h;
        s_sb[q][0] = sx0; s_sb[q][1] = sy0; s_sb[q][2] = sx1; s_sb[q][3] = sy1;
        float4 so; so.x = sx0; so.y = sy0; so.z = sx1; so.w = sy1;
        ((float4*)out_boxes)[(size_t)b * 2 * Q_ + q] = so;

        float4 ob4 = ((const float4*)obj_boxes)[(size_t)b * Q_ + q];
        float ox0 = (ob4.x - 0.5f * ob4.z) * img_w;
        float oy0 = (ob4.y - 0.5f * ob4.w) * img_h;
        float ox1 = (ob4.x + 0.5f * ob4.z) * img_w;
        float oy1 = (ob4.y + 0.5f * ob4.w) * img_h;
        s_ob[q][0] = ox0; s_ob[q][1] = oy0; s_ob[q][2] = ox1; s_ob[q][3] = oy1;
        float4 oo; oo.x = ox0; oo.y = oy0; oo.z = ox1; oo.w = oy1;
        ((float4*)out_boxes)[(size_t)b * 2 * Q_ + Q_ + q] = oo;

        out_labels[(size_t)b * 2 * Q_ + q]      = 0.f;
        out_labels[(size_t)b * 2 * Q_ + Q_ + q] = (float)lbl;

        s_conf[q][0] = 0u; s_conf[q][1] = 0u; s_conf[q][2] = 0u; s_conf[q][3] = 0u;
    }
    __syncthreads();

    // ---- conflict bitmask: same label AND min(iou_sb, iou_ob) > 0.7 ----
    for (int p = tid; p < Q_ * Q_; p += 256) {
        int j = p / Q_, k = p - j * Q_;
        if (j >= k) continue;
        if (s_label[j] != s_label[k]) continue;                 // cheap early-out
        if (!(iou_f(s_sb[j], s_sb[k]) > THR)) continue;
        if (!(iou_f(s_ob[j], s_ob[k]) > THR)) continue;
        atomicOr(&s_conf[j][k >> 5], 1u << (k & 31));
        atomicOr(&s_conf[k][j >> 5], 1u << (j & 31));
    }
    __syncthreads();

    if (tid == 0) {
        int m = 0;
        for (int q = 0; q < Q_; q++)                            // ascending order!
            if (s_conf[q][0] | s_conf[q][1] | s_conf[q][2] | s_conf[q][3])
                s_ql[m++] = (unsigned char)q;
        s_m = m;
    }
    __syncthreads();

    int m = s_m;
    if (m == 0) return;   // >99.9% of blocks exit here

    int nw = (m + 31) >> 5;
    // Compact adjacency over the conflicted subset (diagonal cleared)
    for (int p = tid; p < m * nw; p += 256) {
        int i = p / nw, w = p - i * nw;
        int qi = s_ql[i];
        unsigned bits = 0;
        int jend = min(m, (w + 1) << 5);
        for (int j = (w << 5); j < jend; j++) {
            if (j == i) continue;
            int qj = s_ql[j];
            if ((s_conf[qi][qj >> 5] >> (qj & 31)) & 1u) bits |= 1u << (j & 31);
        }
        s_adj[i][w] = bits;
    }
    __syncthreads();

    float* base = out + (size_t)b * Q_ * V_;
    for (int v = tid; v < V_; v += 256) {
        unsigned alive[4] = {0, 0, 0, 0};
        unsigned supp[4]  = {0, 0, 0, 0};
        for (int w = 0; w < nw; w++) alive[w] = 0xffffffffu;
        int rem = m & 31;
        if (rem) alive[nw - 1] = (1u << rem) - 1u;

        for (;;) {
            unsigned any = 0;
            for (int w = 0; w < nw; w++) any |= alive[w];
            if (!any) break;

            // selection-max == greedy in stable descending-sort order:
            // scan ascending original index with strict '>' -> ties pick lowest index
            int best = -1; float bs = -CUDART_INF_F;
            for (int i = 0; i < m; i++) {
                if ((alive[i >> 5] >> (i & 31)) & 1u) {
                    float s = base[(int)s_ql[i] * V_ + v];
                    if (s > bs) { bs = s; best = i; }
                }
            }
            if (best < 0) break;  // safety (all-NaN)

            for (int w = 0; w < nw; w++) {
                unsigned k = alive[w] & s_adj[best][w];
                supp[w]  |= k;
                alive[w] &= ~k;
            }
            alive[best >> 5] &= ~(1u << (best & 31));
        }

        for (int i = 0; i < m; i++)
            if ((supp[i >> 5] >> (i & 31)) & 1u)
                base[(int)s_ql[i] * V_ + v] -= 1.0f;
    }
}

extern "C" void kernel_launch(void* const* d_in, const int* in_sizes, int n_in,
                              void* d_out, int out_size)
{
    const float* obj_logits  = (const float*)d_in[0];
    const float* verb_logits = (const float*)d_in[1];
    const float* sub_boxes   = (const float*)d_in[2];
    const float* obj_boxes   = (const float*)d_in[3];
    const int*   tsz         = (const int*)d_in[4];
    float* out = (float*)d_out;

    kernF<<<(B_ * Q_) / 8, 256>>>(obj_logits, verb_logits, out);
    kernG<<<B_, 256>>>(sub_boxes, obj_boxes, tsz, out);
}

// round 15
// speedup vs baseline: 2.0836x; 1.0442x over previous
#include <cuda_runtime.h>
#include <math_constants.h>

#define B_ 1024
#define Q_ 100
#define C_ 81
#define NCLS 80
#define V_ 117
#define THR 0.7f

// Scratch (no dynamic allocation allowed)
__device__ int g_label[B_ * Q_];

__device__ __forceinline__ float iou_f(const float* a, const float* b) {
    float area1 = (a[2] - a[0]) * (a[3] - a[1]);
    float area2 = (b[2] - b[0]) * (b[3] - b[1]);
    float ltx = fmaxf(a[0], b[0]), lty = fmaxf(a[1], b[1]);
    float rbx = fminf(a[2], b[2]), rby = fminf(a[3], b[3]);
    float w = fmaxf(rbx - ltx, 0.f), h = fmaxf(rby - lty, 0.f);
    float inter = w * h;
    float uni = area1 + area2 - inter;
    return inter / uni;  // 0/0 -> NaN, NaN > THR is false (matches JAX)
}

// ---------------------------------------------------------------------------
// Kernel F (fused): one warp per query.
//   - softmax over C=81, max/argmax over first 80 (score ends up in ALL lanes)
//   - immediately streams vs[q, :] = sigmoid(verb[q, :]) * score
// ---------------------------------------------------------------------------
__global__ __launch_bounds__(256)
void kernF(const float* __restrict__ obj_logits,
           const float* __restrict__ verb_logits,
           float* __restrict__ out)
{
    int g    = blockIdx.x * 8 + (threadIdx.x >> 5);   // global query id, < B_*Q_
    int lane = threadIdx.x & 31;

    const float* lg = obj_logits + (size_t)g * C_;
    float l0 = lg[lane];                    // c in [0,32)
    float l1 = lg[lane + 32];               // c in [32,64)
    bool  has2 = (lane + 64) < C_;          // c in [64,81)
    float l2 = has2 ? lg[lane + 64] : -CUDART_INF_F;

    float mx = fmaxf(l0, fmaxf(l1, l2));
    #pragma unroll
    for (int o = 16; o; o >>= 1) mx = fmaxf(mx, __shfl_xor_sync(0xffffffffu, mx, o));

    float e = __expf(l0 - mx) + __expf(l1 - mx) + (has2 ? __expf(l2 - mx) : 0.f);
    #pragma unroll
    for (int o = 16; o; o >>= 1) e += __shfl_xor_sync(0xffffffffu, e, o);

    // argmax over c < 80 (exclude last class); ties -> lowest index (stable)
    float bv = l0; int bi = lane;
    if (l1 > bv) { bv = l1; bi = lane + 32; }
    if ((lane + 64) < NCLS && l2 > bv) { bv = l2; bi = lane + 64; }
    #pragma unroll
    for (int o = 16; o; o >>= 1) {
        float ov = __shfl_xor_sync(0xffffffffu, bv, o);
        int   oi = __shfl_xor_sync(0xffffffffu, bi, o);
        if (ov > bv || (ov == bv && oi < bi)) { bv = ov; bi = oi; }
    }

    // xor-reduction leaves identical (bv, e, mx) in every lane
    float score = __fdividef(__expf(bv - mx), e);

    if (lane == 0) {
        float* out_scores = out + (size_t)B_ * Q_ * V_;
        out_scores[g] = score;
        g_label[g]    = bi;
    }

    // ---- fused vs = sigmoid(verb) * score for this query's 117 classes ----
    const float* vb = verb_logits + (size_t)g * V_;
    float*       vo = out         + (size_t)g * V_;
    #pragma unroll
    for (int i = lane; i < V_; i += 32) {
        float x = vb[i];
        vo[i] = __fdividef(score, 1.f + __expf(-x));
    }
}

// ---------------------------------------------------------------------------
// Kernel G (fused): per-image boxes/labels + ballot-based conflict graph +
// in-block PNMS repair (rare path; nearly all blocks skip it entirely).
// ---------------------------------------------------------------------------
__global__ __launch_bounds__(256)
void kernG(const float* __restrict__ sub_boxes,
           const float* __restrict__ obj_boxes,
           const int*   __restrict__ tsz,
           float* __restrict__ out)
{
    int b    = blockIdx.x;
    int tid  = threadIdx.x;
    int lane = tid & 31;
    int warp = tid >> 5;

    __shared__ int           s_label[128];     // padded to 128, pad = -1
    __shared__ float         s_sb[Q_][4];
    __shared__ float         s_ob[Q_][4];
    __shared__ unsigned      s_conf[Q_][4];    // valid only for conflicted rows
    __shared__ unsigned      s_has[4];
    __shared__ int           s_m;
    __shared__ unsigned char s_ql[Q_];
    __shared__ unsigned      s_adj[Q_][4];

    if (tid < 4) s_has[tid] = 0u;
    if (tid >= Q_ && tid < 128) s_label[tid] = -1;

    float img_h = (float)tsz[b * 2 + 0];
    float img_w = (float)tsz[b * 2 + 1];

    float* out_scores = out + (size_t)B_ * Q_ * V_;
    float* out_labels = out_scores + (size_t)B_ * Q_;
    float* out_boxes  = out_labels + (size_t)B_ * 2 * Q_;

    for (int q = tid; q < Q_; q += 256) {
        int lbl = g_label[b * Q_ + q];
        s_label[q] = lbl;

        float4 sb4 = ((const float4*)sub_boxes)[(size_t)b * Q_ + q];
        float sx0 = (sb4.x - 0.5f * sb4.z) * img_w;
        float sy0 = (sb4.y - 0.5f * sb4.w) * img_h;
        float sx1 = (sb4.x + 0.5f * sb4.z) * img_w;
        float sy1 = (sb4.y + 0.5f * sb4.w) * img_h;
        s_sb[q][0] = sx0; s_sb[q][1] = sy0; s_sb[q][2] = sx1; s_sb[q][3] = sy1;
        float4 so; so.x = sx0; so.y = sy0; so.z = sx1; so.w = sy1;
        ((float4*)out_boxes)[(size_t)b * 2 * Q_ + q] = so;

        float4 ob4 = ((const float4*)obj_boxes)[(size_t)b * Q_ + q];
        float ox0 = (ob4.x - 0.5f * ob4.z) * img_w;
        float oy0 = (ob4.y - 0.5f * ob4.w) * img_h;
        float ox1 = (ob4.x + 0.5f * ob4.z) * img_w;
        float oy1 = (ob4.y + 0.5f * ob4.w) * img_h;
        s_ob[q][0] = ox0; s_ob[q][1] = oy0; s_ob[q][2] = ox1; s_ob[q][3] = oy1;
        float4 oo; oo.x = ox0; oo.y = oy0; oo.z = ox1; oo.w = oy1;
        ((float4*)out_boxes)[(size_t)b * 2 * Q_ + Q_ + q] = oo;

        out_labels[(size_t)b * 2 * Q_ + q]      = 0.f;
        out_labels[(size_t)b * 2 * Q_ + Q_ + q] = (float)lbl;
    }
    __syncthreads();

    // ---- ballot-based conflict detection: warp owns rows j = warp, warp+8,.. ----
    {
        int lab0 = s_label[lane];
        int lab1 = s_label[lane + 32];
        int lab2 = s_label[lane + 64];
        int lab3 = s_label[lane + 96];     // -1 for lane >= 4 (pad)

        for (int j = warp; j < Q_; j += 8) {
            int lj = s_label[j];
            unsigned m0 = __ballot_sync(0xffffffffu, lab0 == lj);
            unsigned m1 = __ballot_sync(0xffffffffu, lab1 == lj);
            unsigned m2 = __ballot_sync(0xffffffffu, lab2 == lj);
            unsigned m3 = __ballot_sync(0xffffffffu, lab3 == lj);
            // clear the diagonal bit
            if (j < 32)       m0 &= ~(1u << j);
            else if (j < 64)  m1 &= ~(1u << (j - 32));
            else if (j < 96)  m2 &= ~(1u << (j - 64));
            else              m3 &= ~(1u << (j - 96));

            if (!(m0 | m1 | m2 | m3)) continue;   // warp-uniform; vast majority

            // rare: IoU only for label-matching candidates
            bool r0 = ((m0 >> lane) & 1) &&
                      (iou_f(s_sb[j], s_sb[lane]) > THR) &&
                      (iou_f(s_ob[j], s_ob[lane]) > THR);
            bool r1 = ((m1 >> lane) & 1) &&
                      (iou_f(s_sb[j], s_sb[lane + 32]) > THR) &&
                      (iou_f(s_ob[j], s_ob[lane + 32]) > THR);
            bool r2 = ((m2 >> lane) & 1) &&
                      (iou_f(s_sb[j], s_sb[lane + 64]) > THR) &&
                      (iou_f(s_ob[j], s_ob[lane + 64]) > THR);
            bool r3 = (lane + 96 < Q_) && ((m3 >> lane) & 1) &&
                      (iou_f(s_sb[j], s_sb[lane + 96]) > THR) &&
                      (iou_f(s_ob[j], s_ob[lane + 96]) > THR);

            unsigned c0 = __ballot_sync(0xffffffffu, r0);
            unsigned c1 = __ballot_sync(0xffffffffu, r1);
            unsigned c2 = __ballot_sync(0xffffffffu, r2);
            unsigned c3 = __ballot_sync(0xffffffffu, r3);

            if ((c0 | c1 | c2 | c3) && lane == 0) {
                s_conf[j][0] = c0; s_conf[j][1] = c1;
                s_conf[j][2] = c2; s_conf[j][3] = c3;
                atomicOr(&s_has[j >> 5], 1u << (j & 31));
            }
        }
    }
    __syncthreads();

    if (tid == 0) {
        int m = 0;
        #pragma unroll
        for (int w = 0; w < 4; w++) {           // ascending order preserved
            unsigned bits = s_has[w];
            while (bits) {
                int q = __ffs(bits) - 1;
                bits &= bits - 1;
                s_ql[m++] = (unsigned char)(w * 32 + q);
            }
        }
        s_m = m;
    }
    __syncthreads();

    int m = s_m;
    if (m == 0) return;   // >99.9% of blocks exit here

    int nw = (m + 31) >> 5;
    // Compact adjacency over the conflicted subset (diagonal already clear)
    for (int p = tid; p < m * nw; p += 256) {
        int i = p / nw, w = p - i * nw;
        int qi = s_ql[i];
        unsigned bits = 0;
        int jend = min(m, (w + 1) << 5);
        for (int j = (w << 5); j < jend; j++) {
            if (j == i) continue;
            int qj = s_ql[j];
            if ((s_conf[qi][qj >> 5] >> (qj & 31)) & 1u) bits |= 1u << (j & 31);
        }
        s_adj[i][w] = bits;
    }
    __syncthreads();

    float* base = out + (size_t)b * Q_ * V_;
    for (int v = tid; v < V_; v += 256) {
        unsigned alive[4] = {0, 0, 0, 0};
        unsigned supp[4]  = {0, 0, 0, 0};
        for (int w = 0; w < nw; w++) alive[w] = 0xffffffffu;
        int rem = m & 31;
        if (rem) alive[nw - 1] = (1u << rem) - 1u;

        for (;;) {
            unsigned any = 0;
            for (int w = 0; w < nw; w++) any |= alive[w];
            if (!any) break;

            // selection-max == greedy in stable descending-sort order:
            // scan ascending original index with strict '>' -> ties pick lowest index
            int best = -1; float bs = -CUDART_INF_F;
            for (int i = 0; i < m; i++) {
                if ((alive[i >> 5] >> (i & 31)) & 1u) {
                    float s = base[(int)s_ql[i] * V_ + v];
                    if (s > bs) { bs = s; best = i; }
                }
            }
            if (best < 0) break;  // safety (all-NaN)

            for (int w = 0; w < nw; w++) {
                unsigned k = alive[w] & s_adj[best][w];
                supp[w]  |= k;
                alive[w] &= ~k;
            }
            alive[best >> 5] &= ~(1u << (best & 31));
        }

        for (int i = 0; i < m; i++)
            if ((supp[i >> 5] >> (i & 31)) & 1u)
                base[(int)s_ql[i] * V_ + v] -= 1.0f;
    }
}

extern "C" void kernel_launch(void* const* d_in, const int* in_sizes, int n_in,
                              void* d_out, int out_size)
{
    const float* obj_logits  = (const float*)d_in[0];
    const float* verb_logits = (const float*)d_in[1];
    const float* sub_boxes   = (const float*)d_in[2];
    const float* obj_boxes   = (const float*)d_in[3];
    const int*   tsz         = (const int*)d_in[4];
    float* out = (float*)d_out;

    kernF<<<(B_ * Q_) / 8, 256>>>(obj_logits, verb_logits, out);
    kernG<<<B_, 256>>>(sub_boxes, obj_boxes, tsz, out);
}